// round 10
// baseline (speedup 1.0000x reference)
#include <cuda_runtime.h>
#include <cstdint>

// ---------------------------------------------------------------------------
// out[i, j] = f(j-1) - f(j),  f(j) = relu(1 - relu(x_full[j+1] - x_i) /
//                                         (x_full[j+1] - x_full[j] + 1e-9))
// sentinels f(-1)=1, f(n_full-1)=0; nonzeros only in j in [k-2, k+5].
// SM store issue caps STG streams at ~5.4 TB/s (measured R2..R9).  So:
// assemble 4-row stripes in SMEM (zeros + <=8 patched values per row) and
// write them with cp.async.bulk S2G — the async engine streams HBM while
// the SM only patches ~32 floats per 32.8 KB stripe.  Double buffered.
// Stripe byte size 16*n_full and offset s*16*n_full are multiples of 16.
// ---------------------------------------------------------------------------

__device__ __forceinline__ uint32_t smem_u32(const void* p) {
    uint32_t a;
    asm("{ .reg .u64 t; cvta.to.shared.u64 t, %1; cvt.u32.u64 %0, t; }"
        : "=r"(a) : "l"(p));
    return a;
}

__device__ __forceinline__ float evalf_s(const float* __restrict__ sxf,
                                         int j, int n, float x) {
    if (j < 0) return 1.0f;
    if (j >= n - 1) return 0.0f;
    float xa = sxf[j];
    float xb = sxf[j + 1];
    float t  = fmaxf(0.f, xb - x);
    return fmaxf(0.f, 1.0f - t / (xb - xa + 1e-9f));
}

__device__ __forceinline__ float value_s(const float* __restrict__ sxf,
                                         int c, int n, float x) {
    return evalf_s(sxf, c - 1, n, x) - evalf_s(sxf, c, n, x);
}

__global__ void __launch_bounds__(128, 2)
fused_tma_kernel(const float* __restrict__ x_eval,
                 const float* __restrict__ x_full,
                 float* __restrict__ out,
                 int n_points, int n_full) {
    extern __shared__ float smem[];
    float* bufs[2] = { smem, smem + 4 * n_full };  // two 4-row stripe buffers
    float* sxf     = smem + 8 * n_full;            // staged knots

    // one-time: stage knots, zero both stripe buffers (float4, 16B aligned)
    for (int i = threadIdx.x; i < n_full; i += 128)
        sxf[i] = x_full[i];
    {
        float4* b4 = reinterpret_cast<float4*>(smem);
        int n4 = (8 * n_full) >> 2;                // 8*n_full % 4 == 0
        const float4 z = make_float4(0.f, 0.f, 0.f, 0.f);
        for (int i = threadIdx.x; i < n4; i += 128)
            b4[i] = z;
    }
    __syncthreads();
    if (threadIdx.x >= 32) return;                 // warp 0 runs the pipeline
    int lane = threadIdx.x;

    int nstripes = n_points >> 2;
    int prev_lo[2] = { 1, 1 }, prev_hi[2] = { 0, 0 };
    uint32_t stripe_bytes = 16u * (uint32_t)n_full;

    int it = 0;
    for (int s = blockIdx.x; s < nstripes; s += gridDim.x, ++it) {
        int b = it & 1;
        float* sb = bufs[b];

        // ensure the bulk store issued 2 iters ago (same buffer) finished
        // reading SMEM before we modify it.  (<=1 group left pending)
        asm volatile("cp.async.bulk.wait_group.read 1;" ::: "memory");
        __syncwarp();

        if (lane < 4) {
            // restore previous patch of this buffer to zero
            float* row = sb + lane * n_full;
            for (int j = prev_lo[b]; j <= prev_hi[b]; ++j)
                row[j] = 0.f;

            // locate interval for this stripe's row and patch exact values
            float x = __ldg(x_eval + 4 * s + lane);
            int lo = 0, hi = n_full;
            while (lo < hi) {
                int mid = (lo + hi) >> 1;
                if (sxf[mid] <= x) lo = mid + 1;
                else hi = mid;
            }
            int k = lo - 1;
            k = (k < 0) ? 0 : k;
            if (k > n_full - 2) k = n_full - 2;
            int j0 = (k - 2 < 0) ? 0 : (k - 2);
            int j1 = (k + 5 > n_full - 1) ? (n_full - 1) : (k + 5);
            for (int j = j0; j <= j1; ++j)
                row[j] = value_s(sxf, j, n_full, x);
            prev_lo[b] = j0;
            prev_hi[b] = j1;
        }
        __syncwarp();

        if (lane == 0) {
            asm volatile("fence.proxy.async.shared::cta;" ::: "memory");
            uint64_t gdst = (uint64_t)out + (uint64_t)s * stripe_bytes;
            uint32_t ssrc = smem_u32(sb);
            asm volatile(
                "cp.async.bulk.global.shared::cta.bulk_group [%0], [%1], %2;"
                :: "l"(gdst), "r"(ssrc), "r"(stripe_bytes) : "memory");
            asm volatile("cp.async.bulk.commit_group;" ::: "memory");
        }
        __syncwarp();
    }
    asm volatile("cp.async.bulk.wait_group.read 0;" ::: "memory");

    // leftover rows (n_points % 4): exact formula everywhere, CTA 0 only
    if (blockIdx.x == 0) {
        for (int rr = nstripes * 4; rr < n_points; ++rr) {
            float x = __ldg(x_eval + rr);
            long long rb = (long long)rr * n_full;
            for (int c = lane; c < n_full; c += 32)
                out[rb + c] = value_s(sxf, c, n_full, x);
        }
    }
}

extern "C" void kernel_launch(void* const* d_in, const int* in_sizes, int n_in,
                              void* d_out, int out_size) {
    const float* x_eval = (const float*)d_in[0];  // (n_points, 1) float32
    const float* x_full = (const float*)d_in[1];  // (n_full,)    float32 sorted
    float* out = (float*)d_out;                   // (n_points, n_full) float32
    (void)out_size;

    int n_points = in_sizes[0];
    int n_full   = in_sizes[1];

    // SMEM: 2 stripe buffers (4 rows each) + staged knots
    size_t smem = (size_t)(8 * n_full + n_full) * sizeof(float) + 64;
    static int attr_done = 0;
    if (!attr_done) {
        cudaFuncSetAttribute(fused_tma_kernel,
                             cudaFuncAttributeMaxDynamicSharedMemorySize,
                             (int)smem);
        attr_done = 1;
    }

    int blocks = 152 * 2;                          // persistent, 2 CTAs/SM
    int nstripes = n_points >> 2;
    if (blocks > nstripes && nstripes > 0) blocks = nstripes;
    if (blocks < 1) blocks = 1;

    fused_tma_kernel<<<blocks, 128, smem>>>(x_eval, x_full, out,
                                            n_points, n_full);
}

// round 11
// speedup vs baseline: 1.7755x; 1.7755x over previous
#include <cuda_runtime.h>

// ---------------------------------------------------------------------------
// out[i, j] = f(j-1) - f(j),  f(j) = relu(1 - relu(x_full[j+1] - x_i) /
//                                         (x_full[j+1] - x_full[j] + 1e-9))
// sentinels f(-1)=1, f(n_full-1)=0; nonzeros only in j in [k-2, k+5].
// Plan: proven stcs zero kernel (~5.9 TB/s) + massively parallel scatter
// (1 warp/row, 32-ary ballot search, lanes write the 8 window elements)
// that hides inside the zero kernel's L2 writeback drain.
// ---------------------------------------------------------------------------

__global__ void zero_kernel(float4* __restrict__ out4, int n4,
                            float* __restrict__ out, int rem) {
    int i = blockIdx.x * blockDim.x + threadIdx.x;
    if (i < n4)
        __stcs(out4 + i, make_float4(0.f, 0.f, 0.f, 0.f));
    if (i == 0)
        for (int r = 0; r < rem; ++r) out[4 * n4 + r] = 0.f;
}

__device__ __forceinline__ float evalf_g(const float* __restrict__ xf,
                                         int j, int n, float x) {
    if (j < 0) return 1.0f;
    if (j >= n - 1) return 0.0f;
    float xa = __ldg(xf + j);
    float xb = __ldg(xf + j + 1);
    float t  = fmaxf(0.f, xb - x);
    return fmaxf(0.f, 1.0f - t / (xb - xa + 1e-9f));
}

__global__ void __launch_bounds__(256)
scatter_kernel(const float* __restrict__ x_eval,
               const float* __restrict__ x_full,
               float* __restrict__ out,
               int n_points, int n_full) {
    int gwarp = (blockIdx.x * blockDim.x + threadIdx.x) >> 5;
    int lane  = threadIdx.x & 31;
    if (gwarp >= n_points) return;

    float x = __ldg(x_eval + gwarp);

    // ---- 32-ary ballot search: k0 = max{m : x_full[m] <= x}, else -1 -----
    const unsigned FULL = 0xffffffffu;
    int n  = n_full;
    int s1 = (n + 31) >> 5;                         // 65 @ n=2049
    int m1 = lane * s1;
    bool t1 = (m1 <= n - 1) && (__ldg(x_full + min(m1, n - 1)) <= x);
    unsigned b1 = __ballot_sync(FULL, t1);
    int k0;
    if (b1 == 0) {
        k0 = -1;
    } else {
        int A    = (31 - __clz(b1)) * s1;           // x_full[A] <= x
        int rem  = min(s1, n - A);
        int s2   = (rem + 31) >> 5;                 // <= 3
        bool t2  = (lane * s2 < rem) &&
                   (__ldg(x_full + min(A + lane * s2, n - 1)) <= x);
        unsigned b2 = __ballot_sync(FULL, t2);      // lane0 always set
        int A2   = A + (31 - __clz(b2)) * s2;
        int rem2 = min(s2, rem - ((31 - __clz(b2)) * s2));
        bool t3  = (lane < rem2) &&
                   (__ldg(x_full + min(A2 + lane, n - 1)) <= x);
        unsigned b3 = __ballot_sync(FULL, t3);      // lane0 always set
        k0 = A2 + (31 - __clz(b3));
    }
    int k = k0 < 0 ? 0 : k0;
    if (k > n - 2) k = n - 2;
    int j0 = (k - 2 < 0) ? 0 : (k - 2);
    int j1 = (k + 5 > n - 1) ? (n - 1) : (k + 5);
    int cnt = j1 - j0 + 1;                          // <= 8

    // ---- lanes 0..cnt-1 each write one window element --------------------
    if (lane < cnt) {
        int c = j0 + lane;
        float v = evalf_g(x_full, c - 1, n, x) - evalf_g(x_full, c, n, x);
        out[gwarp * n + c] = v;
    }
}

extern "C" void kernel_launch(void* const* d_in, const int* in_sizes, int n_in,
                              void* d_out, int out_size) {
    const float* x_eval = (const float*)d_in[0];  // (n_points, 1) float32
    const float* x_full = (const float*)d_in[1];  // (n_full,)    float32 sorted
    float* out = (float*)d_out;                   // (n_points, n_full) float32

    int n_points = in_sizes[0];
    int n_full   = in_sizes[1];

    // 1) zero-fill: proven fastest writer (one stcs STG.128 per thread)
    int n4  = out_size >> 2;
    int rem = out_size & 3;
    int zb  = (n4 + 255) / 256;
    if (zb < 1) zb = 1;
    zero_kernel<<<zb, 256>>>((float4*)out, n4, (float*)out, rem);

    // 2) scatter: 1 warp/row, 4096 blocks -> overlaps the L2 drain
    int threads = 256;
    int blocks  = (n_points * 32 + threads - 1) / threads;
    scatter_kernel<<<blocks, threads>>>(x_eval, x_full, out,
                                        n_points, n_full);
}